// round 15
// baseline (speedup 1.0000x reference)
#include <cuda_runtime.h>
#include <cuda_fp16.h>
#include <math.h>
#include <stdint.h>

#define BNN   81920
#define NEDGE 327680
#define NT    16
#define MT    (NT * BNN)

// ---------------- static device scratch ----------------
__device__ __align__(256) float  g_deg[BNN];
__device__ __align__(256) float  g_dinv[BNN];
__device__ __align__(256) int    g_rowptr[BNN + 1];
__device__ __align__(256) int    g_fill[BNN];
__device__ __align__(256) int    g_bsum[80];
__device__ __align__(256) int    g_boff[80];
__device__ __align__(256) int2   g_csr[NEDGE];
__device__ __align__(256) __half g_Xh[(size_t)MT * 64];
__device__ __align__(256) __half g_P1a[(size_t)MT * 64];
__device__ __align__(256) __half g_P2a[(size_t)MT * 64];
__device__ __align__(256) __half g_GxA[(size_t)MT * 192];
__device__ __align__(256) __half g_P3[BNN * 64];
__device__ __align__(256) __half g_P4[BNN * 64];
__device__ __align__(256) __half g_Z[BNN * 64];
__device__ __align__(256) __half g_HR[BNN * 64];
__device__ __align__(256) __half g_Hst[BNN * 64];
__device__ __align__(256) __half g_WBx[192 * 192];
__device__ __align__(256) __half g_WBh[128 * 192];
__device__ __align__(256) __half g_WB2[64 * 192];
__device__ __align__(256) __half g_WB3[640 * 1280];
__device__ __align__(256) __half g_WB4[320 * 640];
__device__ __align__(256) float  g_bc1[192];
__device__ __align__(256) __half g_M1[4096 * 640];
__device__ __align__(256) __half g_M2[4096 * 320];

// ---------------- helpers ----------------
__device__ __forceinline__ uint32_t su32(const void* p) {
    uint32_t a;
    asm("{ .reg .u64 t; cvta.to.shared.u64 t, %1; cvt.u32.u64 %0, t; }" : "=r"(a) : "l"(p));
    return a;
}
__device__ __forceinline__ void cp16(uint32_t dst, const void* src) {
    asm volatile("cp.async.cg.shared.global [%0], [%1], 16;" :: "r"(dst), "l"(src));
}
__device__ __forceinline__ void cp_commit() {
    asm volatile("cp.async.commit_group;" ::: "memory");
}
template <int N>
__device__ __forceinline__ void cp_wait() {
    asm volatile("cp.async.wait_group %0;" :: "n"(N) : "memory");
}
// m16n8k16 fp16 MMA, fp32 accumulate
__device__ __forceinline__ void mma16(float* d, const uint32_t* a, const uint32_t* b) {
    asm volatile(
        "mma.sync.aligned.m16n8k16.row.col.f32.f16.f16.f32 "
        "{%0,%1,%2,%3}, {%4,%5,%6,%7}, {%8,%9}, {%0,%1,%2,%3};"
        : "+f"(d[0]), "+f"(d[1]), "+f"(d[2]), "+f"(d[3])
        : "r"(a[0]), "r"(a[1]), "r"(a[2]), "r"(a[3]), "r"(b[0]), "r"(b[1]));
}
__device__ __forceinline__ float sigf(float x) { return 1.f / (1.f + expf(-x)); }

// ---------------- graph preprocessing ----------------
__global__ void k_degcnt(const int* __restrict__ src, const int* __restrict__ dst,
                         const float* __restrict__ w) {
    int e = blockIdx.x * 256 + threadIdx.x;
    atomicAdd(&g_deg[src[e]], w[e]);
    atomicAdd(&g_fill[dst[e]], 1);
}
__global__ void k_dinv() {
    int n = blockIdx.x * 256 + threadIdx.x;
    float d = g_deg[n];
    g_dinv[n] = (d > 0.f) ? rsqrtf(d) : 0.f;
}
__global__ void k_scanA() {
    int tid = threadIdx.x, lane = tid & 31, wp = tid >> 5, b = blockIdx.x;
    __shared__ int wsum[32];
    int v = g_fill[b * 1024 + tid], x = v;
#pragma unroll
    for (int o = 1; o < 32; o <<= 1) {
        int n = __shfl_up_sync(0xffffffffu, x, o);
        if (lane >= o) x += n;
    }
    if (lane == 31) wsum[wp] = x;
    __syncthreads();
    if (wp == 0) {
        int y = wsum[lane];
#pragma unroll
        for (int o = 1; o < 32; o <<= 1) {
            int n = __shfl_up_sync(0xffffffffu, y, o);
            if (lane >= o) y += n;
        }
        wsum[lane] = y;
    }
    __syncthreads();
    int base = (wp > 0) ? wsum[wp - 1] : 0;
    g_rowptr[b * 1024 + tid] = base + x - v;
    if (tid == 1023) g_bsum[b] = base + x;
}
__global__ void k_scanB() {
    int lane = threadIdx.x;
    int carry = 0;
    for (int base = 0; base < 80; base += 32) {
        int v = (base + lane < 80) ? g_bsum[base + lane] : 0, x = v;
#pragma unroll
        for (int o = 1; o < 32; o <<= 1) {
            int n = __shfl_up_sync(0xffffffffu, x, o);
            if (lane >= o) x += n;
        }
        if (base + lane < 80) g_boff[base + lane] = carry + x - v;
        carry += __shfl_sync(0xffffffffu, x, 31);
    }
    if (lane == 0) g_rowptr[BNN] = carry;
}
__global__ void k_scanC() {
    int i = blockIdx.x * 1024 + threadIdx.x;
    int r = g_rowptr[i] + g_boff[blockIdx.x];
    g_rowptr[i] = r;
    g_fill[i] = r;
}
__global__ void k_fillcsr(const int* __restrict__ src, const int* __restrict__ dst,
                          const float* __restrict__ w) {
    int e = blockIdx.x * 256 + threadIdx.x;
    int s = src[e], d = dst[e];
    float wn = -g_dinv[s] * w[e] * g_dinv[d];
    int pos = atomicAdd(&g_fill[d], 1);
    g_csr[pos] = make_int2(s, __float_as_int(wn));
}

// ---------------- weight packing (folded Chebyshev, fp16) ----------------
__global__ void k_packW(const float* __restrict__ Wxz, const float* __restrict__ Wxr,
                        const float* __restrict__ Wxh, const float* __restrict__ Whz,
                        const float* __restrict__ Whr, const float* __restrict__ Whh,
                        const float* __restrict__ bxz, const float* __restrict__ bxr,
                        const float* __restrict__ bxh, const float* __restrict__ bhz,
                        const float* __restrict__ bhr, const float* __restrict__ bhh,
                        const float* __restrict__ W1, const float* __restrict__ W2) {
    int idx = blockIdx.x * 256 + threadIdx.x;
    if (idx < 36864) {
        int n = idx / 192, k = idx % 192, kb = k >> 6, j = k & 63, c = n & 63;
        const float* W = (n < 64) ? Wxz : ((n < 128) ? Wxr : Wxh);
        float v = (kb == 0) ? W[j * 64 + c] - W[2 * 4096 + j * 64 + c]
                : (kb == 1) ? W[4096 + j * 64 + c]
                            : 2.f * W[2 * 4096 + j * 64 + c];
        g_WBx[idx] = __float2half_rn(v);
    } else if (idx < 61440) {
        int t = idx - 36864;
        int n = t / 192, k = t % 192, kb = k >> 6, j = k & 63, c = n & 63;
        const float* W = (n < 64) ? Whz : Whr;
        float v = (kb == 0) ? W[j * 64 + c] - W[2 * 4096 + j * 64 + c]
                : (kb == 1) ? W[4096 + j * 64 + c]
                            : 2.f * W[2 * 4096 + j * 64 + c];
        g_WBh[t] = __float2half_rn(v);
    } else if (idx < 73728) {
        int t = idx - 61440;
        int n = t / 192, k = t % 192, kb = k >> 6, j = k & 63;
        float v = (kb == 0) ? Whh[j * 64 + n] - Whh[2 * 4096 + j * 64 + n]
                : (kb == 1) ? Whh[4096 + j * 64 + n]
                            : 2.f * Whh[2 * 4096 + j * 64 + n];
        g_WB2[t] = __float2half_rn(v);
    } else if (idx < 892928) {
        int t = idx - 73728;
        int n = t / 1280, k = t % 1280;
        g_WB3[t] = __float2half_rn(W1[k * 640 + n]);
    } else if (idx < 1097728) {
        int t = idx - 892928;
        int n = t / 640, k = t % 640;
        g_WB4[t] = __float2half_rn(W2[k * 320 + n]);
    } else if (idx < 1097920) {
        int c = idx - 1097728;
        float v;
        if (c < 64) v = bxz[c] + bhz[c];
        else if (c < 128) v = bxr[c - 64] + bhr[c - 64];
        else v = bxh[c - 128] + bhh[c - 128];
        g_bc1[c] = v;
    }
}

// ---------------- fp32 -> fp16 convert (8 elems/thread) ----------------
__global__ void k_cvt(const float4* __restrict__ X, uint4* __restrict__ out) {
    int i = blockIdx.x * 256 + threadIdx.x;
    float4 a = X[i * 2], b = X[i * 2 + 1];
    uint4 r;
    __half2* o = (__half2*)&r;
    o[0] = __floats2half2_rn(a.x, a.y);
    o[1] = __floats2half2_rn(a.z, a.w);
    o[2] = __floats2half2_rn(b.x, b.y);
    o[3] = __floats2half2_rn(b.z, b.w);
    out[i] = r;
}

// ---------------- sparse propagation: out = L * X (fp16 data) --------------
__global__ void k_prop(const uint4* __restrict__ X, uint4* __restrict__ out) {
    int i = blockIdx.x * 128 + threadIdx.x;
    int node = i >> 3, l = i & 7;   // 8 lanes/node, 8 halves each
    int s = g_rowptr[node], e = g_rowptr[node + 1];
    float acc[8];
#pragma unroll
    for (int j = 0; j < 8; j++) acc[j] = 0.f;
    for (int k = s; k < e; k++) {
        int2 c0 = g_csr[k];
        float w = __int_as_float(c0.y);
        uint4 v = X[c0.x * 8 + l];
        const __half2* h = (const __half2*)&v;
#pragma unroll
        for (int j = 0; j < 4; j++) {
            float2 f = __half22float2(h[j]);
            acc[2 * j] += w * f.x;
            acc[2 * j + 1] += w * f.y;
        }
    }
    uint4 r;
    __half2* o = (__half2*)&r;
#pragma unroll
    for (int j = 0; j < 4; j++) o[j] = __floats2half2_rn(acc[2 * j], acc[2 * j + 1]);
    out[node * 8 + l] = r;
}

// ---------------- fp16 mma GEMM, cp.async double-buffered ----------------
// A = [a0 | a1 | a2] (MULTI, each [M][64] halves) or single a0 with astride.
// B stored [N][K] halves. EPI 0: gates (N=128: Z | HR). EPI 1: GRU -> H.
// EPI 2: relu + bias -> C(half). EPI 3: raw -> C(half).
struct Args {
    const __half* a0; const __half* a1; const __half* a2;
    int astride; int nk; int ktot;
    const __half* B; const float* bias;
    __half* C; int ldc;
    const __half* G;
};

#define SH  40              // SMEM row stride in halves (80 B)
#define AWH (128 * SH)      // halves per A buffer

template <int NTILE, int EPI, bool MULTI>
__global__ __launch_bounds__(256) void k_mma(Args a) {
    extern __shared__ __half smh[];
    constexpr int BWH = NTILE * SH;
    __half* Asm = smh;
    __half* Bsm = smh + 2 * AWH;
    const uint32_t sA = su32(Asm), sB = su32(Bsm);
    const int tid = threadIdx.x, wid = tid >> 5, lane = tid & 31;
    constexpr int MTW = (NTILE == 128) ? 4 : 2;
    constexpr int NTW = (NTILE == 192) ? 12 : 4;
    const int wm = (NTILE == 128) ? (wid & 1) * 64 : (wid & 3) * 32;
    const int wn = (NTILE == 128) ? (wid >> 1) * 32
                 : (NTILE == 192) ? (wid >> 2) * 96 : (wid >> 2) * 32;
    const int m0 = blockIdx.y * 128, n0 = blockIdx.x * NTILE;

    float acc[MTW][NTW][4];
#pragma unroll
    for (int i = 0; i < MTW; i++)
#pragma unroll
        for (int j = 0; j < NTW; j++)
#pragma unroll
            for (int q = 0; q < 4; q++) acc[i][j][q] = 0.f;

    auto issue = [&](int c) {
        const __half* Ap;
        int koff, rs;
        if (MULTI) {
            int sel = c >> 1;
            Ap = (sel == 0) ? a.a0 : (sel == 1) ? a.a1 : a.a2;
            koff = (c & 1) * 32;
            rs = 64;
        } else {
            Ap = a.a0; koff = c * 32; rs = a.astride;
        }
        const uint32_t abase = sA + (uint32_t)(c & 1) * AWH * 2;
        const uint32_t bbase = sB + (uint32_t)(c & 1) * BWH * 2;
#pragma unroll
        for (int q = 0; q < 2; q++) {           // A: 512 16B units
            int u = tid + q * 256;
            int row = u >> 2, j = u & 3;        // 4 units (64B) per row
            cp16(abase + row * (SH * 2) + j * 16,
                 Ap + (size_t)(m0 + row) * rs + koff + j * 8);
        }
#pragma unroll
        for (int q = 0; q < NTILE / 64; q++) {  // B: NTILE*4 units
            int u = tid + q * 256;
            int row = u >> 2, j = u & 3;
            cp16(bbase + row * (SH * 2) + j * 16,
                 a.B + (size_t)(n0 + row) * a.ktot + c * 32 + j * 8);
        }
        cp_commit();
    };

    issue(0);
    for (int c = 0; c < a.nk; c++) {
        if (c + 1 < a.nk) { issue(c + 1); cp_wait<1>(); }
        else              { cp_wait<0>(); }
        __syncthreads();
        const __half* Ab = Asm + (c & 1) * AWH;
        const __half* Bb = Bsm + (c & 1) * BWH;
#pragma unroll
        for (int ks = 0; ks < 2; ks++) {
            const int kb = ks * 16;
            const int kc = kb + 2 * (lane & 3);
            uint32_t af[MTW][4], bf[NTW][2];
#pragma unroll
            for (int mt = 0; mt < MTW; mt++) {
                int r = wm + mt * 16 + (lane >> 2);
                af[mt][0] = *(const uint32_t*)(Ab + r * SH + kc);
                af[mt][1] = *(const uint32_t*)(Ab + (r + 8) * SH + kc);
                af[mt][2] = *(const uint32_t*)(Ab + r * SH + kc + 8);
                af[mt][3] = *(const uint32_t*)(Ab + (r + 8) * SH + kc + 8);
            }
#pragma unroll
            for (int nt = 0; nt < NTW; nt++) {
                int n = wn + nt * 8 + (lane >> 2);
                bf[nt][0] = *(const uint32_t*)(Bb + n * SH + kc);
                bf[nt][1] = *(const uint32_t*)(Bb + n * SH + kc + 8);
            }
#pragma unroll
            for (int mt = 0; mt < MTW; mt++)
#pragma unroll
                for (int nt = 0; nt < NTW; nt++) mma16(acc[mt][nt], af[mt], bf[nt]);
        }
        __syncthreads();
    }

#pragma unroll
    for (int mt = 0; mt < MTW; mt++) {
#pragma unroll
        for (int nt = 0; nt < NTW; nt++) {
            int colb = wn + nt * 8 + 2 * (lane & 3);
            int r0 = m0 + wm + mt * 16 + (lane >> 2);
            int r1 = r0 + 8;
            float2 v0 = make_float2(acc[mt][nt][0], acc[mt][nt][1]);
            float2 v1 = make_float2(acc[mt][nt][2], acc[mt][nt][3]);
            if (EPI == 0) {
                float2 b = *(const float2*)(g_bc1 + colb);
                float2 g0 = __half22float2(*(const __half2*)(a.G + (size_t)r0 * 192 + colb));
                float2 g1 = __half22float2(*(const __half2*)(a.G + (size_t)r1 * 192 + colb));
                if (colb < 64) {
                    *(__half2*)(g_Z + (size_t)r0 * 64 + colb) =
                        __floats2half2_rn(sigf(v0.x + g0.x + b.x), sigf(v0.y + g0.y + b.y));
                    *(__half2*)(g_Z + (size_t)r1 * 64 + colb) =
                        __floats2half2_rn(sigf(v1.x + g1.x + b.x), sigf(v1.y + g1.y + b.y));
                } else {
                    int cc = colb - 64;
                    float2 h0 = __half22float2(*(const __half2*)(g_Hst + (size_t)r0 * 64 + cc));
                    float2 h1 = __half22float2(*(const __half2*)(g_Hst + (size_t)r1 * 64 + cc));
                    *(__half2*)(g_HR + (size_t)r0 * 64 + cc) =
                        __floats2half2_rn(h0.x * sigf(v0.x + g0.x + b.x),
                                          h0.y * sigf(v0.y + g0.y + b.y));
                    *(__half2*)(g_HR + (size_t)r1 * 64 + cc) =
                        __floats2half2_rn(h1.x * sigf(v1.x + g1.x + b.x),
                                          h1.y * sigf(v1.y + g1.y + b.y));
                }
            } else if (EPI == 1) {
                float2 g0 = __half22float2(*(const __half2*)(a.G + (size_t)r0 * 192 + 128 + colb));
                float2 g1 = __half22float2(*(const __half2*)(a.G + (size_t)r1 * 192 + 128 + colb));
                float2 b = *(const float2*)(g_bc1 + 128 + colb);
                float2 z0 = __half22float2(*(const __half2*)(g_Z + (size_t)r0 * 64 + colb));
                float2 z1 = __half22float2(*(const __half2*)(g_Z + (size_t)r1 * 64 + colb));
                float2 h0 = __half22float2(*(const __half2*)(g_Hst + (size_t)r0 * 64 + colb));
                float2 h1 = __half22float2(*(const __half2*)(g_Hst + (size_t)r1 * 64 + colb));
                float t0x = tanhf(v0.x + g0.x + b.x), t0y = tanhf(v0.y + g0.y + b.y);
                float t1x = tanhf(v1.x + g1.x + b.x), t1y = tanhf(v1.y + g1.y + b.y);
                *(__half2*)(g_Hst + (size_t)r0 * 64 + colb) =
                    __floats2half2_rn(fmaxf(z0.x * h0.x + (1.f - z0.x) * t0x, 0.f),
                                      fmaxf(z0.y * h0.y + (1.f - z0.y) * t0y, 0.f));
                *(__half2*)(g_Hst + (size_t)r1 * 64 + colb) =
                    __floats2half2_rn(fmaxf(z1.x * h1.x + (1.f - z1.x) * t1x, 0.f),
                                      fmaxf(z1.y * h1.y + (1.f - z1.y) * t1y, 0.f));
            } else if (EPI == 2) {
                float2 b = make_float2(a.bias[n0 + colb], a.bias[n0 + colb + 1]);
                *(__half2*)(a.C + (size_t)r0 * a.ldc + n0 + colb) =
                    __floats2half2_rn(fmaxf(v0.x + b.x, 0.f), fmaxf(v0.y + b.y, 0.f));
                *(__half2*)(a.C + (size_t)r1 * a.ldc + n0 + colb) =
                    __floats2half2_rn(fmaxf(v1.x + b.x, 0.f), fmaxf(v1.y + b.y, 0.f));
            } else {
                *(__half2*)(a.C + (size_t)r0 * a.ldc + n0 + colb) =
                    __floats2half2_rn(v0.x, v0.y);
                *(__half2*)(a.C + (size_t)r1 * a.ldc + n0 + colb) =
                    __floats2half2_rn(v1.x, v1.y);
            }
        }
    }
}

// ---------------- t = 0 special case (H0 = 0) ----------------
__global__ void k_step0(const __half* __restrict__ G) {
    int i = blockIdx.x * 256 + threadIdx.x;
    int r = i >> 6, c = i & 63;
    float z = sigf(__half2float(G[(size_t)r * 192 + c]) + g_bc1[c]);
    float ht = tanhf(__half2float(G[(size_t)r * 192 + 128 + c]) + g_bc1[128 + c]);
    g_Hst[i] = __float2half_rn(fmaxf((1.f - z) * ht, 0.f));
}

// ---------------- final layer + softmax ----------------
__global__ void k_out(const __half* __restrict__ A, const float* __restrict__ W3,
                      const float* __restrict__ b3, float* __restrict__ out) {
    int warp = threadIdx.x >> 5, lane = threadIdx.x & 31;
    int row = blockIdx.x * 8 + warp;
    float s0 = 0.f, s1 = 0.f;
    for (int k = lane; k < 320; k += 32) {
        float a = __half2float(A[row * 320 + k]);
        s0 += a * W3[k * 2];
        s1 += a * W3[k * 2 + 1];
    }
#pragma unroll
    for (int o = 16; o; o >>= 1) {
        s0 += __shfl_xor_sync(0xffffffffu, s0, o);
        s1 += __shfl_xor_sync(0xffffffffu, s1, o);
    }
    if (lane == 0) {
        float l0 = s0 + b3[0], l1 = s1 + b3[1];
        float m = fmaxf(l0, l1);
        float e0 = expf(l0 - m), e1 = expf(l1 - m);
        float inv = 1.f / (e0 + e1);
        out[row * 2] = e0 * inv;
        out[row * 2 + 1] = e1 * inv;
    }
}

// ---------------- launch ----------------
extern "C" void kernel_launch(void* const* d_in, const int* in_sizes, int n_in,
                              void* d_out, int out_size) {
    const float* x = (const float*)d_in[0];
    const int* ei = (const int*)d_in[1];
    const float* ew = (const float*)d_in[2];
    const float* Wxz = (const float*)d_in[3];  const float* bxz = (const float*)d_in[4];
    const float* Whz = (const float*)d_in[5];  const float* bhz = (const float*)d_in[6];
    const float* Wxr = (const float*)d_in[7];  const float* bxr = (const float*)d_in[8];
    const float* Whr = (const float*)d_in[9];  const float* bhr = (const float*)d_in[10];
    const float* Wxh = (const float*)d_in[11]; const float* bxh = (const float*)d_in[12];
    const float* Whh = (const float*)d_in[13]; const float* bhh = (const float*)d_in[14];
    const float* W1 = (const float*)d_in[15];  const float* b1 = (const float*)d_in[16];
    const float* W2 = (const float*)d_in[17];  const float* b2 = (const float*)d_in[18];
    const float* W3 = (const float*)d_in[19];  const float* b3 = (const float*)d_in[20];
    float* out = (float*)d_out;
    const int* src = ei;
    const int* dst = ei + NEDGE;

    float *pDeg;
    __half *pXh, *pP1a, *pP2a, *pGxA, *pP3, *pP4, *pHR, *pH;
    __half *pWBx, *pWBh, *pWB2, *pWB3, *pWB4, *pM1, *pM2;
    int* pFill;
    cudaGetSymbolAddress((void**)&pDeg, g_deg);
    cudaGetSymbolAddress((void**)&pFill, g_fill);
    cudaGetSymbolAddress((void**)&pXh, g_Xh);
    cudaGetSymbolAddress((void**)&pP1a, g_P1a);
    cudaGetSymbolAddress((void**)&pP2a, g_P2a);
    cudaGetSymbolAddress((void**)&pGxA, g_GxA);
    cudaGetSymbolAddress((void**)&pP3, g_P3);
    cudaGetSymbolAddress((void**)&pP4, g_P4);
    cudaGetSymbolAddress((void**)&pHR, g_HR);
    cudaGetSymbolAddress((void**)&pH, g_Hst);
    cudaGetSymbolAddress((void**)&pWBx, g_WBx);
    cudaGetSymbolAddress((void**)&pWBh, g_WBh);
    cudaGetSymbolAddress((void**)&pWB2, g_WB2);
    cudaGetSymbolAddress((void**)&pWB3, g_WB3);
    cudaGetSymbolAddress((void**)&pWB4, g_WB4);
    cudaGetSymbolAddress((void**)&pM1, g_M1);
    cudaGetSymbolAddress((void**)&pM2, g_M2);

    const int SMB64  = (2 * AWH + 2 * 64 * SH) * 2;   // 30720
    const int SMB128 = (2 * AWH + 2 * 128 * SH) * 2;  // 40960
    const int SMB192 = (2 * AWH + 2 * 192 * SH) * 2;  // 51200
    cudaFuncSetAttribute(k_mma<192, 3, true>,  cudaFuncAttributeMaxDynamicSharedMemorySize, SMB192);
    cudaFuncSetAttribute(k_mma<128, 0, true>,  cudaFuncAttributeMaxDynamicSharedMemorySize, SMB128);
    cudaFuncSetAttribute(k_mma<64, 1, true>,   cudaFuncAttributeMaxDynamicSharedMemorySize, SMB64);
    cudaFuncSetAttribute(k_mma<128, 2, false>, cudaFuncAttributeMaxDynamicSharedMemorySize, SMB128);
    cudaFuncSetAttribute(k_mma<64, 2, false>,  cudaFuncAttributeMaxDynamicSharedMemorySize, SMB64);

    cudaStream_t s2;
    cudaStreamCreateWithFlags(&s2, cudaStreamNonBlocking);
    cudaEvent_t evFork;
    cudaEventCreateWithFlags(&evFork, cudaEventDisableTiming);
    cudaEvent_t evX[NT];
    for (int t = 0; t < NT; t++) cudaEventCreateWithFlags(&evX[t], cudaEventDisableTiming);

    // ---- preprocessing (stream 0) ----
    cudaMemsetAsync(pDeg, 0, BNN * sizeof(float));
    cudaMemsetAsync(pFill, 0, BNN * sizeof(int));
    k_degcnt<<<NEDGE / 256, 256>>>(src, dst, ew);
    k_dinv<<<BNN / 256, 256>>>();
    k_scanA<<<80, 1024>>>();
    k_scanB<<<1, 32>>>();
    k_scanC<<<80, 1024>>>();
    k_fillcsr<<<NEDGE / 256, 256>>>(src, dst, ew);
    k_packW<<<(1097920 + 255) / 256, 256>>>(Wxz, Wxr, Wxh, Whz, Whr, Whh,
                                            bxz, bxr, bxh, bhz, bhr, bhh, W1, W2);

    // ---- fork: X-side per-timestep chunks on s2 ----
    cudaEventRecord(evFork, 0);
    cudaStreamWaitEvent(s2, evFork, 0);

    const int cvtGrid = BNN * 64 / (256 * 8);  // 2560
    const dim3 pg1(BNN * 8 / 128, 1);          // 5120 blocks
    for (int t = 0; t < NT; t++) {
        const float* xt = x + (size_t)t * BNN * 64;
        __half* xht = pXh + (size_t)t * BNN * 64;
        __half* p1t = pP1a + (size_t)t * BNN * 64;
        __half* p2t = pP2a + (size_t)t * BNN * 64;
        __half* gxt = pGxA + (size_t)t * BNN * 192;
        k_cvt<<<cvtGrid, 256, 0, s2>>>((const float4*)xt, (uint4*)xht);
        k_prop<<<pg1, 128, 0, s2>>>((const uint4*)xht, (uint4*)p1t);
        k_prop<<<pg1, 128, 0, s2>>>((const uint4*)p1t, (uint4*)p2t);
        Args ax{};
        ax.a0 = xht; ax.a1 = p1t; ax.a2 = p2t; ax.nk = 6; ax.ktot = 192;
        ax.B = pWBx; ax.C = gxt; ax.ldc = 192;
        k_mma<192, 3, true><<<dim3(1, 640), 256, SMB192, s2>>>(ax);
        cudaEventRecord(evX[t], s2);
    }

    // ---- recurrence (stream 0) ----
    cudaStreamWaitEvent(0, evX[0], 0);
    k_step0<<<BNN * 64 / 256, 256>>>(pGxA);

    Args ah{};
    ah.nk = 6; ah.ktot = 192; ah.B = pWBh;
    Args a2{};
    a2.nk = 6; a2.ktot = 192; a2.B = pWB2;

    for (int t = 1; t < NT; t++) {
        const __half* Gt = pGxA + (size_t)t * BNN * 192;
        k_prop<<<pg1, 128>>>((const uint4*)pH, (uint4*)pP3);
        k_prop<<<pg1, 128>>>((const uint4*)pP3, (uint4*)pP4);
        cudaStreamWaitEvent(0, evX[t], 0);
        ah.a0 = pH; ah.a1 = pP3; ah.a2 = pP4; ah.G = Gt;
        k_mma<128, 0, true><<<dim3(1, 640), 256, SMB128>>>(ah);
        k_prop<<<pg1, 128>>>((const uint4*)pHR, (uint4*)pP3);
        k_prop<<<pg1, 128>>>((const uint4*)pP3, (uint4*)pP4);
        a2.a0 = pHR; a2.a1 = pP3; a2.a2 = pP4; a2.G = Gt;
        k_mma<64, 1, true><<<dim3(1, 640), 256, SMB64>>>(a2);
    }

    // ---- MLP head (H as [4096, 1280] halves) ----
    Args m1{}; m1.a0 = pH; m1.astride = 1280; m1.nk = 40; m1.ktot = 1280;
    m1.B = pWB3; m1.bias = b1; m1.C = pM1; m1.ldc = 640;
    k_mma<128, 2, false><<<dim3(5, 32), 256, SMB128>>>(m1);
    Args m2{}; m2.a0 = pM1; m2.astride = 640; m2.nk = 20; m2.ktot = 640;
    m2.B = pWB4; m2.bias = b2; m2.C = pM2; m2.ldc = 320;
    k_mma<64, 2, false><<<dim3(5, 32), 256, SMB64>>>(m2);
    k_out<<<512, 256>>>(pM2, W3, b3, out);
}

// round 16
// speedup vs baseline: 1.3741x; 1.3741x over previous
#include <cuda_runtime.h>
#include <cuda_fp16.h>
#include <math.h>
#include <stdint.h>

#define BNN   81920
#define NEDGE 327680
#define NT    16
#define MT    (NT * BNN)

// ---------------- static device scratch ----------------
__device__ __align__(256) float  g_deg[BNN];
__device__ __align__(256) float  g_dinv[BNN];
__device__ __align__(256) int    g_rowptr[BNN + 1];
__device__ __align__(256) int    g_fill[BNN];
__device__ __align__(256) int    g_bsum[80];
__device__ __align__(256) int    g_boff[80];
__device__ __align__(256) int2   g_csr[NEDGE];
__device__ __align__(256) __half g_Xh[(size_t)MT * 64];
__device__ __align__(256) __half g_P1a[(size_t)MT * 64];
__device__ __align__(256) __half g_P2a[(size_t)MT * 64];
__device__ __align__(256) __half g_GxA[(size_t)MT * 192];
__device__ __align__(256) __half g_P3[BNN * 64];
__device__ __align__(256) __half g_P4[BNN * 64];
__device__ __align__(256) __half g_Z[BNN * 64];
__device__ __align__(256) __half g_HR[BNN * 64];
__device__ __align__(256) __half g_Hst[BNN * 64];
__device__ __align__(256) __half g_WBx[192 * 192];
__device__ __align__(256) __half g_WBh[128 * 192];
__device__ __align__(256) __half g_WB2[64 * 192];
__device__ __align__(256) __half g_WB3[640 * 1280];
__device__ __align__(256) __half g_WB4[320 * 640];
__device__ __align__(256) float  g_bc1[192];
__device__ __align__(256) __half g_M1[4096 * 640];
__device__ __align__(256) __half g_M2[4096 * 320];

// ---------------- helpers ----------------
__device__ __forceinline__ uint32_t su32(const void* p) {
    uint32_t a;
    asm("{ .reg .u64 t; cvta.to.shared.u64 t, %1; cvt.u32.u64 %0, t; }" : "=r"(a) : "l"(p));
    return a;
}
__device__ __forceinline__ void cp16(uint32_t dst, const void* src) {
    asm volatile("cp.async.cg.shared.global [%0], [%1], 16;" :: "r"(dst), "l"(src));
}
__device__ __forceinline__ void cp_commit() {
    asm volatile("cp.async.commit_group;" ::: "memory");
}
template <int N>
__device__ __forceinline__ void cp_wait() {
    asm volatile("cp.async.wait_group %0;" :: "n"(N) : "memory");
}
__device__ __forceinline__ void mma16(float* d, const uint32_t* a, const uint32_t* b) {
    asm volatile(
        "mma.sync.aligned.m16n8k16.row.col.f32.f16.f16.f32 "
        "{%0,%1,%2,%3}, {%4,%5,%6,%7}, {%8,%9}, {%0,%1,%2,%3};"
        : "+f"(d[0]), "+f"(d[1]), "+f"(d[2]), "+f"(d[3])
        : "r"(a[0]), "r"(a[1]), "r"(a[2]), "r"(a[3]), "r"(b[0]), "r"(b[1]));
}
__device__ __forceinline__ float sigf(float x) { return 1.f / (1.f + expf(-x)); }

// ---------------- graph preprocessing ----------------
__global__ void k_degcnt(const int* __restrict__ src, const int* __restrict__ dst,
                         const float* __restrict__ w) {
    int e = blockIdx.x * 256 + threadIdx.x;
    atomicAdd(&g_deg[src[e]], w[e]);
    atomicAdd(&g_fill[dst[e]], 1);
}
__global__ void k_dinv() {
    int n = blockIdx.x * 256 + threadIdx.x;
    float d = g_deg[n];
    g_dinv[n] = (d > 0.f) ? rsqrtf(d) : 0.f;
}
__global__ void k_scanA() {
    int tid = threadIdx.x, lane = tid & 31, wp = tid >> 5, b = blockIdx.x;
    __shared__ int wsum[32];
    int v = g_fill[b * 1024 + tid], x = v;
#pragma unroll
    for (int o = 1; o < 32; o <<= 1) {
        int n = __shfl_up_sync(0xffffffffu, x, o);
        if (lane >= o) x += n;
    }
    if (lane == 31) wsum[wp] = x;
    __syncthreads();
    if (wp == 0) {
        int y = wsum[lane];
#pragma unroll
        for (int o = 1; o < 32; o <<= 1) {
            int n = __shfl_up_sync(0xffffffffu, y, o);
            if (lane >= o) y += n;
        }
        wsum[lane] = y;
    }
    __syncthreads();
    int base = (wp > 0) ? wsum[wp - 1] : 0;
    g_rowptr[b * 1024 + tid] = base + x - v;
    if (tid == 1023) g_bsum[b] = base + x;
}
__global__ void k_scanB() {
    int lane = threadIdx.x;
    int carry = 0;
    for (int base = 0; base < 80; base += 32) {
        int v = (base + lane < 80) ? g_bsum[base + lane] : 0, x = v;
#pragma unroll
        for (int o = 1; o < 32; o <<= 1) {
            int n = __shfl_up_sync(0xffffffffu, x, o);
            if (lane >= o) x += n;
        }
        if (base + lane < 80) g_boff[base + lane] = carry + x - v;
        carry += __shfl_sync(0xffffffffu, x, 31);
    }
    if (lane == 0) g_rowptr[BNN] = carry;
}
__global__ void k_scanC() {
    int i = blockIdx.x * 1024 + threadIdx.x;
    int r = g_rowptr[i] + g_boff[blockIdx.x];
    g_rowptr[i] = r;
    g_fill[i] = r;
}
__global__ void k_fillcsr(const int* __restrict__ src, const int* __restrict__ dst,
                          const float* __restrict__ w) {
    int e = blockIdx.x * 256 + threadIdx.x;
    int s = src[e], d = dst[e];
    float wn = -g_dinv[s] * w[e] * g_dinv[d];
    int pos = atomicAdd(&g_fill[d], 1);
    g_csr[pos] = make_int2(s, __float_as_int(wn));
}

// ---------------- weight packing (folded Chebyshev, fp16) ----------------
__global__ void k_packW(const float* __restrict__ Wxz, const float* __restrict__ Wxr,
                        const float* __restrict__ Wxh, const float* __restrict__ Whz,
                        const float* __restrict__ Whr, const float* __restrict__ Whh,
                        const float* __restrict__ bxz, const float* __restrict__ bxr,
                        const float* __restrict__ bxh, const float* __restrict__ bhz,
                        const float* __restrict__ bhr, const float* __restrict__ bhh,
                        const float* __restrict__ W1, const float* __restrict__ W2) {
    int idx = blockIdx.x * 256 + threadIdx.x;
    if (idx < 36864) {
        int n = idx / 192, k = idx % 192, kb = k >> 6, j = k & 63, c = n & 63;
        const float* W = (n < 64) ? Wxz : ((n < 128) ? Wxr : Wxh);
        float v = (kb == 0) ? W[j * 64 + c] - W[2 * 4096 + j * 64 + c]
                : (kb == 1) ? W[4096 + j * 64 + c]
                            : 2.f * W[2 * 4096 + j * 64 + c];
        g_WBx[idx] = __float2half_rn(v);
    } else if (idx < 61440) {
        int t = idx - 36864;
        int n = t / 192, k = t % 192, kb = k >> 6, j = k & 63, c = n & 63;
        const float* W = (n < 64) ? Whz : Whr;
        float v = (kb == 0) ? W[j * 64 + c] - W[2 * 4096 + j * 64 + c]
                : (kb == 1) ? W[4096 + j * 64 + c]
                            : 2.f * W[2 * 4096 + j * 64 + c];
        g_WBh[t] = __float2half_rn(v);
    } else if (idx < 73728) {
        int t = idx - 61440;
        int n = t / 192, k = t % 192, kb = k >> 6, j = k & 63;
        float v = (kb == 0) ? Whh[j * 64 + n] - Whh[2 * 4096 + j * 64 + n]
                : (kb == 1) ? Whh[4096 + j * 64 + n]
                            : 2.f * Whh[2 * 4096 + j * 64 + n];
        g_WB2[t] = __float2half_rn(v);
    } else if (idx < 892928) {
        int t = idx - 73728;
        int n = t / 1280, k = t % 1280;
        g_WB3[t] = __float2half_rn(W1[k * 640 + n]);
    } else if (idx < 1097728) {
        int t = idx - 892928;
        int n = t / 640, k = t % 640;
        g_WB4[t] = __float2half_rn(W2[k * 320 + n]);
    } else if (idx < 1097920) {
        int c = idx - 1097728;
        float v;
        if (c < 64) v = bxz[c] + bhz[c];
        else if (c < 128) v = bxr[c - 64] + bhr[c - 64];
        else v = bxh[c - 128] + bhh[c - 128];
        g_bc1[c] = v;
    }
}

// ---------------- fp32 -> fp16 convert (8 elems/thread) ----------------
__global__ void k_cvt(const float4* __restrict__ X, uint4* __restrict__ out) {
    int i = blockIdx.x * 256 + threadIdx.x;
    float4 a = X[i * 2], b = X[i * 2 + 1];
    uint4 r;
    __half2* o = (__half2*)&r;
    o[0] = __floats2half2_rn(a.x, a.y);
    o[1] = __floats2half2_rn(a.z, a.w);
    o[2] = __floats2half2_rn(b.x, b.y);
    o[3] = __floats2half2_rn(b.z, b.w);
    out[i] = r;
}

// ---------------- sparse propagation: out = L * X (fp16, 16 lanes/node) ----
__global__ void k_prop(const uint2* __restrict__ X, uint2* __restrict__ out) {
    int i = blockIdx.x * 128 + threadIdx.x;
    int node = i >> 4, l = i & 15;   // 16 lanes/node, 4 halves each
    int s = g_rowptr[node], e = g_rowptr[node + 1];
    float a0 = 0.f, a1 = 0.f, a2 = 0.f, a3 = 0.f;
    int k = s;
    for (; k + 2 <= e; k += 2) {
        int2 c0 = g_csr[k], c1 = g_csr[k + 1];
        float w0 = __int_as_float(c0.y), w1 = __int_as_float(c1.y);
        uint2 v0 = X[c0.x * 16 + l], v1 = X[c1.x * 16 + l];
        float2 f0 = __half22float2(*(__half2*)&v0.x);
        float2 f1 = __half22float2(*(__half2*)&v0.y);
        float2 g0 = __half22float2(*(__half2*)&v1.x);
        float2 g1 = __half22float2(*(__half2*)&v1.y);
        a0 += w0 * f0.x + w1 * g0.x;
        a1 += w0 * f0.y + w1 * g0.y;
        a2 += w0 * f1.x + w1 * g1.x;
        a3 += w0 * f1.y + w1 * g1.y;
    }
    if (k < e) {
        int2 c0 = g_csr[k];
        float w0 = __int_as_float(c0.y);
        uint2 v0 = X[c0.x * 16 + l];
        float2 f0 = __half22float2(*(__half2*)&v0.x);
        float2 f1 = __half22float2(*(__half2*)&v0.y);
        a0 += w0 * f0.x; a1 += w0 * f0.y; a2 += w0 * f1.x; a3 += w0 * f1.y;
    }
    uint2 r;
    *(__half2*)&r.x = __floats2half2_rn(a0, a1);
    *(__half2*)&r.y = __floats2half2_rn(a2, a3);
    out[node * 16 + l] = r;
}

// ---------------- fp16 mma GEMM, K-chunk=64 halves, double-buffered --------
// A = [a0 | a1 | a2] (MULTI: chunk c = buffer c, 64 halves) or a0 + astride.
// B stored [N][K] halves. EPI 0: gates (N=128: Z | HR). EPI 1: GRU -> H.
// EPI 2: relu + bias -> C(half). EPI 3: raw -> C(half).
struct Args {
    const __half* a0; const __half* a1; const __half* a2;
    int astride; int nk; int ktot;
    const __half* B; const float* bias;
    __half* C; int ldc;
    const __half* G;
};

#define SH  72              // SMEM row stride in halves (144 B)
#define AWH (128 * SH)

template <int NTILE, int EPI, bool MULTI>
__global__ __launch_bounds__(256) void k_mma(Args a) {
    extern __shared__ __half smh[];
    constexpr int BWH = NTILE * SH;
    __half* Asm = smh;
    __half* Bsm = smh + 2 * AWH;
    const uint32_t sA = su32(Asm), sB = su32(Bsm);
    const int tid = threadIdx.x, wid = tid >> 5, lane = tid & 31;
    constexpr int MTW = (NTILE == 128) ? 4 : 2;
    constexpr int NTW = (NTILE == 192) ? 12 : 4;
    const int wm = (NTILE == 128) ? (wid & 1) * 64 : (wid & 3) * 32;
    const int wn = (NTILE == 128) ? (wid >> 1) * 32
                 : (NTILE == 192) ? (wid >> 2) * 96 : (wid >> 2) * 32;
    const int m0 = blockIdx.y * 128, n0 = blockIdx.x * NTILE;

    float acc[MTW][NTW][4];
#pragma unroll
    for (int i = 0; i < MTW; i++)
#pragma unroll
        for (int j = 0; j < NTW; j++)
#pragma unroll
            for (int q = 0; q < 4; q++) acc[i][j][q] = 0.f;

    auto issue = [&](int c) {
        const __half* Ap;
        int koff, rs;
        if (MULTI) {
            Ap = (c == 0) ? a.a0 : (c == 1) ? a.a1 : a.a2;
            koff = 0;
            rs = 64;
        } else {
            Ap = a.a0; koff = c * 64; rs = a.astride;
        }
        const uint32_t abase = sA + (uint32_t)(c & 1) * AWH * 2;
        const uint32_t bbase = sB + (uint32_t)(c & 1) * BWH * 2;
#pragma unroll
        for (int q = 0; q < 4; q++) {           // A: 1024 16B units
            int u = tid + q * 256;
            int row = u >> 3, j = u & 7;        // 8 units (128B) per row
            cp16(abase + row * (SH * 2) + j * 16,
                 Ap + (size_t)(m0 + row) * rs + koff + j * 8);
        }
#pragma unroll
        for (int q = 0; q < NTILE / 32; q++) {  // B: NTILE*8 units
            int u = tid + q * 256;
            int row = u >> 3, j = u & 7;
            cp16(bbase + row * (SH * 2) + j * 16,
                 a.B + (size_t)(n0 + row) * a.ktot + c * 64 + j * 8);
        }
        cp_commit();
    };

    issue(0);
    for (int c = 0; c < a.nk; c++) {
        if (c + 1 < a.nk) { issue(c + 1); cp_wait<1>(); }
        else              { cp_wait<0>(); }
        __syncthreads();
        const __half* Ab = Asm + (c & 1) * AWH;
        const __half* Bb = Bsm + (c & 1) * BWH;
#pragma unroll
        for (int ks = 0; ks < 4; ks++) {
            const int kc = ks * 16 + 2 * (lane & 3);
            uint32_t af[MTW][4], bf[NTW][2];
#pragma unroll
            for (int mt = 0; mt < MTW; mt++) {
                int r = wm + mt * 16 + (lane >> 2);
                af[mt][0] = *(const uint32_t*)(Ab + r * SH + kc);
                af[mt][1] = *(const uint32_t*)(Ab + (r + 8) * SH + kc);
                af[mt][2] = *(const uint32_t*)(Ab + r * SH + kc + 8);
                af[mt][3] = *(const uint32_t*)(Ab + (r + 8) * SH + kc + 8);
            }
#pragma unroll
            for (int nt = 0; nt < NTW; nt++) {
                int n = wn + nt * 8 + (lane >> 2);
                bf[nt][0] = *(const uint32_t*)(Bb + n * SH + kc);
                bf[nt][1] = *(const uint32_t*)(Bb + n * SH + kc + 8);
            }
#pragma unroll
            for (int mt = 0; mt < MTW; mt++)
#pragma unroll
                for (int nt = 0; nt < NTW; nt++) mma16(acc[mt][nt], af[mt], bf[nt]);
        }
        __syncthreads();
    }

#pragma unroll
    for (int mt = 0; mt < MTW; mt++) {
#pragma unroll
        for (int nt = 0; nt < NTW; nt++) {
            int colb = wn + nt * 8 + 2 * (lane & 3);
            int r0 = m0 + wm + mt * 16 + (lane >> 2);
            int r1 = r0 + 8;
            float2 v0 = make_float2(acc[mt][nt][0], acc[mt][nt][1]);
            float2 v1 = make_float2(acc[mt][nt][2], acc[mt][nt][3]);
            if (EPI == 0) {
                float2 b = *(const float2*)(g_bc1 + colb);
                float2 g0 = __half22float2(*(const __half2*)(a.G + (size_t)r0 * 192 + colb));
                float2 g1 = __half22float2(*(const __half2*)(a.G + (size_t)r1 * 192 + colb));
                if (colb < 64) {
                    *(__half2*)(g_Z + (size_t)r0 * 64 + colb) =
                        __floats2half2_rn(sigf(v0.x + g0.x + b.x), sigf(v0.y + g0.y + b.y));
                    *(__half2*)(g_Z + (size_t)r1 * 64 + colb) =
                        __floats2half2_rn(sigf(v1.x + g1.x + b.x), sigf(v1.y + g1.y + b.y));
                } else {
                    int cc = colb - 64;
                    float2 h0 = __half22float2(*(const __half2*)(g_Hst + (size_t)r0 * 64 + cc));
                    float2 h1 = __half22float2(*(const __half2*)(g_Hst + (size_t)r1 * 64 + cc));
                    *(__half2*)(g_HR + (size_t)r0 * 64 + cc) =
                        __floats2half2_rn(h0.x * sigf(v0.x + g0.x + b.x),
                                          h0.y * sigf(v0.y + g0.y + b.y));
                    *(__half2*)(g_HR + (size_t)r1 * 64 + cc) =
                        __floats2half2_rn(h1.x * sigf(v1.x + g1.x + b.x),
                                          h1.y * sigf(v1.y + g1.y + b.y));
                }
            } else if (EPI == 1) {
                float2 g0 = __half22float2(*(const __half2*)(a.G + (size_t)r0 * 192 + 128 + colb));
                float2 g1 = __half22float2(*(const __half2*)(a.G + (size_t)r1 * 192 + 128 + colb));
                float2 b = *(const float2*)(g_bc1 + 128 + colb);
                float2 z0 = __half22float2(*(const __half2*)(g_Z + (size_t)r0 * 64 + colb));
                float2 z1 = __half22float2(*(const __half2*)(g_Z + (size_t)r1 * 64 + colb));
                float2 h0 = __half22float2(*(const __half2*)(g_Hst + (size_t)r0 * 64 + colb));
                float2 h1 = __half22float2(*(const __half2*)(g_Hst + (size_t)r1 * 64 + colb));
                float t0x = tanhf(v0.x + g0.x + b.x), t0y = tanhf(v0.y + g0.y + b.y);
                float t1x = tanhf(v1.x + g1.x + b.x), t1y = tanhf(v1.y + g1.y + b.y);
                *(__half2*)(g_Hst + (size_t)r0 * 64 + colb) =
                    __floats2half2_rn(fmaxf(z0.x * h0.x + (1.f - z0.x) * t0x, 0.f),
                                      fmaxf(z0.y * h0.y + (1.f - z0.y) * t0y, 0.f));
                *(__half2*)(g_Hst + (size_t)r1 * 64 + colb) =
                    __floats2half2_rn(fmaxf(z1.x * h1.x + (1.f - z1.x) * t1x, 0.f),
                                      fmaxf(z1.y * h1.y + (1.f - z1.y) * t1y, 0.f));
            } else if (EPI == 2) {
                float2 b = make_float2(a.bias[n0 + colb], a.bias[n0 + colb + 1]);
                *(__half2*)(a.C + (size_t)r0 * a.ldc + n0 + colb) =
                    __floats2half2_rn(fmaxf(v0.x + b.x, 0.f), fmaxf(v0.y + b.y, 0.f));
                *(__half2*)(a.C + (size_t)r1 * a.ldc + n0 + colb) =
                    __floats2half2_rn(fmaxf(v1.x + b.x, 0.f), fmaxf(v1.y + b.y, 0.f));
            } else {
                *(__half2*)(a.C + (size_t)r0 * a.ldc + n0 + colb) =
                    __floats2half2_rn(v0.x, v0.y);
                *(__half2*)(a.C + (size_t)r1 * a.ldc + n0 + colb) =
                    __floats2half2_rn(v1.x, v1.y);
            }
        }
    }
}

// ---------------- t = 0 special case (H0 = 0) ----------------
__global__ void k_step0(const __half* __restrict__ G) {
    int i = blockIdx.x * 256 + threadIdx.x;
    int r = i >> 6, c = i & 63;
    float z = sigf(__half2float(G[(size_t)r * 192 + c]) + g_bc1[c]);
    float ht = tanhf(__half2float(G[(size_t)r * 192 + 128 + c]) + g_bc1[128 + c]);
    g_Hst[i] = __float2half_rn(fmaxf((1.f - z) * ht, 0.f));
}

// ---------------- final layer + softmax ----------------
__global__ void k_out(const __half* __restrict__ A, const float* __restrict__ W3,
                      const float* __restrict__ b3, float* __restrict__ out) {
    int warp = threadIdx.x >> 5, lane = threadIdx.x & 31;
    int row = blockIdx.x * 8 + warp;
    float s0 = 0.f, s1 = 0.f;
    for (int k = lane; k < 320; k += 32) {
        float a = __half2float(A[row * 320 + k]);
        s0 += a * W3[k * 2];
        s1 += a * W3[k * 2 + 1];
    }
#pragma unroll
    for (int o = 16; o; o >>= 1) {
        s0 += __shfl_xor_sync(0xffffffffu, s0, o);
        s1 += __shfl_xor_sync(0xffffffffu, s1, o);
    }
    if (lane == 0) {
        float l0 = s0 + b3[0], l1 = s1 + b3[1];
        float m = fmaxf(l0, l1);
        float e0 = expf(l0 - m), e1 = expf(l1 - m);
        float inv = 1.f / (e0 + e1);
        out[row * 2] = e0 * inv;
        out[row * 2 + 1] = e1 * inv;
    }
}

// ---------------- launch ----------------
extern "C" void kernel_launch(void* const* d_in, const int* in_sizes, int n_in,
                              void* d_out, int out_size) {
    const float* x = (const float*)d_in[0];
    const int* ei = (const int*)d_in[1];
    const float* ew = (const float*)d_in[2];
    const float* Wxz = (const float*)d_in[3];  const float* bxz = (const float*)d_in[4];
    const float* Whz = (const float*)d_in[5];  const float* bhz = (const float*)d_in[6];
    const float* Wxr = (const float*)d_in[7];  const float* bxr = (const float*)d_in[8];
    const float* Whr = (const float*)d_in[9];  const float* bhr = (const float*)d_in[10];
    const float* Wxh = (const float*)d_in[11]; const float* bxh = (const float*)d_in[12];
    const float* Whh = (const float*)d_in[13]; const float* bhh = (const float*)d_in[14];
    const float* W1 = (const float*)d_in[15];  const float* b1 = (const float*)d_in[16];
    const float* W2 = (const float*)d_in[17];  const float* b2 = (const float*)d_in[18];
    const float* W3 = (const float*)d_in[19];  const float* b3 = (const float*)d_in[20];
    float* out = (float*)d_out;
    const int* src = ei;
    const int* dst = ei + NEDGE;

    float* pDeg;
    __half *pXh, *pP1a, *pP2a, *pGxA, *pP3, *pP4, *pHR, *pH;
    __half *pWBx, *pWBh, *pWB2, *pWB3, *pWB4, *pM1, *pM2;
    int* pFill;
    cudaGetSymbolAddress((void**)&pDeg, g_deg);
    cudaGetSymbolAddress((void**)&pFill, g_fill);
    cudaGetSymbolAddress((void**)&pXh, g_Xh);
    cudaGetSymbolAddress((void**)&pP1a, g_P1a);
    cudaGetSymbolAddress((void**)&pP2a, g_P2a);
    cudaGetSymbolAddress((void**)&pGxA, g_GxA);
    cudaGetSymbolAddress((void**)&pP3, g_P3);
    cudaGetSymbolAddress((void**)&pP4, g_P4);
    cudaGetSymbolAddress((void**)&pHR, g_HR);
    cudaGetSymbolAddress((void**)&pH, g_Hst);
    cudaGetSymbolAddress((void**)&pWBx, g_WBx);
    cudaGetSymbolAddress((void**)&pWBh, g_WBh);
    cudaGetSymbolAddress((void**)&pWB2, g_WB2);
    cudaGetSymbolAddress((void**)&pWB3, g_WB3);
    cudaGetSymbolAddress((void**)&pWB4, g_WB4);
    cudaGetSymbolAddress((void**)&pM1, g_M1);
    cudaGetSymbolAddress((void**)&pM2, g_M2);

    const int SMB64  = 2 * (AWH + 64 * SH) * 2;   // 55296
    const int SMB128 = 2 * (AWH + 128 * SH) * 2;  // 73728
    const int SMB192 = 2 * (AWH + 192 * SH) * 2;  // 92160
    cudaFuncSetAttribute(k_mma<192, 3, true>,  cudaFuncAttributeMaxDynamicSharedMemorySize, SMB192);
    cudaFuncSetAttribute(k_mma<128, 0, true>,  cudaFuncAttributeMaxDynamicSharedMemorySize, SMB128);
    cudaFuncSetAttribute(k_mma<64, 1, true>,   cudaFuncAttributeMaxDynamicSharedMemorySize, SMB64);
    cudaFuncSetAttribute(k_mma<128, 2, false>, cudaFuncAttributeMaxDynamicSharedMemorySize, SMB128);
    cudaFuncSetAttribute(k_mma<64, 2, false>,  cudaFuncAttributeMaxDynamicSharedMemorySize, SMB64);

    cudaStream_t s2;
    cudaStreamCreateWithFlags(&s2, cudaStreamNonBlocking);
    cudaEvent_t evFork;
    cudaEventCreateWithFlags(&evFork, cudaEventDisableTiming);
    cudaEvent_t evX[NT];
    for (int t = 0; t < NT; t++) cudaEventCreateWithFlags(&evX[t], cudaEventDisableTiming);

    // ---- preprocessing (stream 0) ----
    cudaMemsetAsync(pDeg, 0, BNN * sizeof(float));
    cudaMemsetAsync(pFill, 0, BNN * sizeof(int));
    k_degcnt<<<NEDGE / 256, 256>>>(src, dst, ew);
    k_dinv<<<BNN / 256, 256>>>();
    k_scanA<<<80, 1024>>>();
    k_scanB<<<1, 32>>>();
    k_scanC<<<80, 1024>>>();
    k_fillcsr<<<NEDGE / 256, 256>>>(src, dst, ew);
    k_packW<<<(1097920 + 255) / 256, 256>>>(Wxz, Wxr, Wxh, Whz, Whr, Whh,
                                            bxz, bxr, bxh, bhz, bhr, bhh, W1, W2);

    // ---- fork: X-side per-timestep chunks on s2 ----
    cudaEventRecord(evFork, 0);
    cudaStreamWaitEvent(s2, evFork, 0);

    const int cvtGrid = BNN * 64 / (256 * 8);  // 2560
    const dim3 pg1(BNN * 16 / 128, 1);         // 10240 blocks
    for (int t = 0; t < NT; t++) {
        const float* xt = x + (size_t)t * BNN * 64;
        __half* xht = pXh + (size_t)t * BNN * 64;
        __half* p1t = pP1a + (size_t)t * BNN * 64;
        __half* p2t = pP2a + (size_t)t * BNN * 64;
        __half* gxt = pGxA + (size_t)t * BNN * 192;
        k_cvt<<<cvtGrid, 256, 0, s2>>>((const float4*)xt, (uint4*)xht);
        k_prop<<<pg1, 128, 0, s2>>>((const uint2*)xht, (uint2*)p1t);
        k_prop<<<pg1, 128, 0, s2>>>((const uint2*)p1t, (uint2*)p2t);
        Args ax{};
        ax.a0 = xht; ax.a1 = p1t; ax.a2 = p2t; ax.nk = 3; ax.ktot = 192;
        ax.B = pWBx; ax.C = gxt; ax.ldc = 192;
        k_mma<192, 3, true><<<dim3(1, 640), 256, SMB192, s2>>>(ax);
        cudaEventRecord(evX[t], s2);
    }

    // ---- recurrence (stream 0) ----
    cudaStreamWaitEvent(0, evX[0], 0);
    k_step0<<<BNN * 64 / 256, 256>>>(pGxA);

    Args ah{};
    ah.nk = 3; ah.ktot = 192; ah.B = pWBh;
    Args a2{};
    a2.nk = 3; a2.ktot = 192; a2.B = pWB2;

    for (int t = 1; t < NT; t++) {
        const __half* Gt = pGxA + (size_t)t * BNN * 192;
        k_prop<<<pg1, 128>>>((const uint2*)pH, (uint2*)pP3);
        k_prop<<<pg1, 128>>>((const uint2*)pP3, (uint2*)pP4);
        cudaStreamWaitEvent(0, evX[t], 0);
        ah.a0 = pH; ah.a1 = pP3; ah.a2 = pP4; ah.G = Gt;
        k_mma<128, 0, true><<<dim3(1, 640), 256, SMB128>>>(ah);
        k_prop<<<pg1, 128>>>((const uint2*)pHR, (uint2*)pP3);
        k_prop<<<pg1, 128>>>((const uint2*)pP3, (uint2*)pP4);
        a2.a0 = pHR; a2.a1 = pP3; a2.a2 = pP4; a2.G = Gt;
        k_mma<64, 1, true><<<dim3(1, 640), 256, SMB64>>>(a2);
    }

    // ---- MLP head (H as [4096, 1280] halves) ----
    Args m1{}; m1.a0 = pH; m1.astride = 1280; m1.nk = 20; m1.ktot = 1280;
    m1.B = pWB3; m1.bias = b1; m1.C = pM1; m1.ldc = 640;
    k_mma<128, 2, false><<<dim3(5, 32), 256, SMB128>>>(m1);
    Args m2{}; m2.a0 = pM1; m2.astride = 640; m2.nk = 10; m2.ktot = 640;
    m2.B = pWB4; m2.bias = b2; m2.C = pM2; m2.ldc = 320;
    k_mma<64, 2, false><<<dim3(5, 32), 256, SMB64>>>(m2);
    k_out<<<512, 256>>>(pM2, W3, b3, out);
}